// round 1
// baseline (speedup 1.0000x reference)
#include <cuda_runtime.h>
#include <cuda_bf16.h>

// Problem constants
#define BATCH      4096
#define INPUT_DIM  1024
#define BOND       32
#define OUT_DIM    512

// Tree: 1024 cores -> 128 group products (x8) -> 16 (x8) -> 1 (x16)
__device__ float g_buf1[128 * BOND * BOND];   // 512 KB
__device__ float g_buf2[16  * BOND * BOND];   // 64 KB
__device__ float g_w[OUT_DIM];                // w = (ones @ Pi cores) @ projection

// Shared-memory layout for the 32x32 chain-product blocks.
// Row stride 36 keeps float4 alignment (multiples of 4) and breaks most bank conflicts.
struct __align__(16) ChainSmem {
    float A[2][BOND][36];   // ping-pong running product, row-major [j][l]
    float Bt[BOND][36];     // next matrix, TRANSPOSED [k][l] so B-column reads are LDS.128
};

// Product of `group` consecutive 32x32 row-major matrices starting at src[base].
// 256 threads: thread owns output row j = tid>>3, cols kt..kt+3 (kt = (tid&7)*4).
// Leaves result in s.A[cur][j][k]; caller must __syncthreads() before reading.
__device__ __forceinline__ int chain_product(ChainSmem& s, const float* __restrict__ src,
                                             int base, int group) {
    const int tid = threadIdx.x;
    const int j  = tid >> 3;
    const int kt = (tid & 7) << 2;

    // First matrix -> A[0], row-major (tid*4 == j*32 + kt)
    {
        float4 v = *(const float4*)(src + (long)base * (BOND * BOND) + tid * 4);
        *(float4*)&s.A[0][j][kt] = v;
    }

    int cur = 0;
    for (int t = 1; t < group; ++t) {
        // Stage next matrix from global (coalesced float4), scatter transposed into Bt.
        float4 v = *(const float4*)(src + (long)(base + t) * (BOND * BOND) + tid * 4);
        __syncthreads();                 // prior iteration done with Bt / A[cur^1]
        s.Bt[kt + 0][j] = v.x;           // element (l=j? no): global idx tid*4 -> row j, col kt
        s.Bt[kt + 1][j] = v.y;           // matrix element M[j][kt+i] stored at Bt[kt+i][j]
        s.Bt[kt + 2][j] = v.z;
        s.Bt[kt + 3][j] = v.w;
        __syncthreads();                 // Bt ready, previous A writes visible

        float a0 = 0.f, a1 = 0.f, a2 = 0.f, a3 = 0.f;
        #pragma unroll
        for (int c = 0; c < 8; ++c) {
            float4 av = *(const float4*)&s.A[cur][j][c * 4];       // broadcast within warp
            float4 b0 = *(const float4*)&s.Bt[kt + 0][c * 4];
            float4 b1 = *(const float4*)&s.Bt[kt + 1][c * 4];
            float4 b2 = *(const float4*)&s.Bt[kt + 2][c * 4];
            float4 b3 = *(const float4*)&s.Bt[kt + 3][c * 4];
            a0 += av.x * b0.x + av.y * b0.y + av.z * b0.z + av.w * b0.w;
            a1 += av.x * b1.x + av.y * b1.y + av.z * b1.z + av.w * b1.w;
            a2 += av.x * b2.x + av.y * b2.y + av.z * b2.z + av.w * b2.w;
            a3 += av.x * b3.x + av.y * b3.y + av.z * b3.z + av.w * b3.w;
        }
        // Write to the other buffer; next iteration's second barrier orders read-after-write.
        *(float4*)&s.A[cur ^ 1][j][kt] = make_float4(a0, a1, a2, a3);
        cur ^= 1;
    }
    return cur;
}

// Level 1: 128 blocks, each computes product of 8 consecutive cores -> g_buf1
__global__ void __launch_bounds__(256) k_chain1(const float* __restrict__ cores) {
    __shared__ ChainSmem s;
    int cur = chain_product(s, cores, blockIdx.x * 8, 8);
    __syncthreads();
    const int tid = threadIdx.x;
    const int j = tid >> 3, kt = (tid & 7) << 2;
    *(float4*)&g_buf1[blockIdx.x * (BOND * BOND) + tid * 4] = *(float4*)&s.A[cur][j][kt];
}

// Level 2: 16 blocks, product of 8 consecutive g_buf1 mats -> g_buf2
__global__ void __launch_bounds__(256) k_chain2() {
    __shared__ ChainSmem s;
    int cur = chain_product(s, g_buf1, blockIdx.x * 8, 8);
    __syncthreads();
    const int tid = threadIdx.x;
    const int j = tid >> 3, kt = (tid & 7) << 2;
    *(float4*)&g_buf2[blockIdx.x * (BOND * BOND) + tid * 4] = *(float4*)&s.A[cur][j][kt];
}

// Level 3: one block folds the remaining 16 matrices, then
// u = ones @ M  (column sums), w = u @ projection -> g_w
__global__ void __launch_bounds__(256) k_finalize(const float* __restrict__ proj) {
    __shared__ ChainSmem s;
    __shared__ float u[BOND];
    int cur = chain_product(s, g_buf2, 0, 16);
    __syncthreads();
    const int tid = threadIdx.x;
    if (tid < BOND) {
        float acc = 0.f;
        #pragma unroll
        for (int jj = 0; jj < BOND; ++jj) acc += s.A[cur][jj][tid];
        u[tid] = acc;
    }
    __syncthreads();
    for (int o = tid; o < OUT_DIM; o += 256) {
        float acc = 0.f;
        #pragma unroll
        for (int k = 0; k < BOND; ++k) acc += u[k] * proj[k * OUT_DIM + o];
        g_w[o] = acc;
    }
}

// Output: one block per batch row. p[b] = prod of 1024 inputs, then rank-1 write.
__global__ void __launch_bounds__(256) k_output(const float* __restrict__ x,
                                                const float* __restrict__ bias,
                                                float* __restrict__ out) {
    const int b   = blockIdx.x;
    const int tid = threadIdx.x;

    // 256 threads x float4 = 1024 elements, fully coalesced
    float4 v = *(const float4*)(x + (long)b * INPUT_DIM + tid * 4);
    float p = v.x * v.y * v.z * v.w;

    // warp product-reduce
    #pragma unroll
    for (int off = 16; off; off >>= 1) p *= __shfl_xor_sync(0xffffffffu, p, off);

    __shared__ float wp[8];
    __shared__ float ptot;
    if ((tid & 31) == 0) wp[tid >> 5] = p;
    __syncthreads();
    if (tid == 0) {
        float t = 1.f;
        #pragma unroll
        for (int i = 0; i < 8; ++i) t *= wp[i];
        ptot = t;
    }
    __syncthreads();
    const float P = ptot;

    // 512 outputs per row, coalesced
    out[(long)b * OUT_DIM + tid]           = P * g_w[tid]           + bias[tid];
    out[(long)b * OUT_DIM + tid + 256]     = P * g_w[tid + 256]     + bias[tid + 256];
}

extern "C" void kernel_launch(void* const* d_in, const int* in_sizes, int n_in,
                              void* d_out, int out_size) {
    const float* inputs = (const float*)d_in[0];   // [4096, 1024]
    const float* cores  = (const float*)d_in[1];   // [1024, 32, 32]
    const float* proj   = (const float*)d_in[2];   // [32, 512]
    const float* bias   = (const float*)d_in[3];   // [512]
    float*       out    = (float*)d_out;           // [4096, 512]

    (void)in_sizes; (void)n_in; (void)out_size;

    k_chain1  <<<128, 256>>>(cores);
    k_chain2  <<<16,  256>>>();
    k_finalize<<<1,   256>>>(proj);
    k_output  <<<BATCH, 256>>>(inputs, bias, out);
}

// round 6
// speedup vs baseline: 3.2017x; 3.2017x over previous
#include <cuda_runtime.h>
#include <cuda_bf16.h>

#define BATCH      4096
#define INPUT_DIM  1024
#define BOND       32
#define OUT_DIM    512

// Tree: 1024 cores -> 128 group products (x8) -> 16 (x8) -> vector chain (16)
__device__ __align__(16) float g_buf1[128 * BOND * BOND];
__device__ __align__(16) float g_buf2[16  * BOND * BOND];
__device__ __align__(16) float g_w[OUT_DIM];

// Shared layout: row stride 36 floats keeps float4 alignment and spreads banks.
struct __align__(16) ChainSmem {
    float A[2][BOND][36];   // ping-pong running product, row-major
    float B[BOND][36];      // staged next matrix, ROW-MAJOR (no transpose needed)
};

// Product of GROUP consecutive row-major 32x32 matrices starting at src[base].
// All GROUP matrices are prefetched into registers first (MLP=GROUP), so no
// global latency is exposed inside the serial loop.
// Thread (j = tid>>3, kt = (tid&7)*4) owns out[j][kt..kt+3].
template<int GROUP>
__device__ __forceinline__ void chain_product_store(const float* __restrict__ src,
                                                    int base,
                                                    float* __restrict__ dst) {
    __shared__ ChainSmem s;
    const int tid = threadIdx.x;
    const int j  = tid >> 3;
    const int kt = (tid & 7) << 2;

    // Prefetch all GROUP matrices (front-batched independent LDG.128)
    float4 m[GROUP];
#pragma unroll
    for (int t = 0; t < GROUP; ++t)
        m[t] = *(const float4*)(src + (size_t)(base + t) * (BOND * BOND) + tid * 4);

    // m[0] -> A[0] (tid*4 == j*32 + kt, row-major)
    *(float4*)&s.A[0][j][kt] = m[0];

    int cur = 0;
#pragma unroll
    for (int t = 1; t < GROUP; ++t) {
        __syncthreads();                    // prior iter done reading s.B; A[cur] visible
        *(float4*)&s.B[j][kt] = m[t];       // stage next matrix, row-major
        __syncthreads();                    // s.B ready

        // out[j][kt+q] = sum_c A[j][c] * B[c][kt+q]
        float a0 = 0.f, a1 = 0.f, a2 = 0.f, a3 = 0.f;
#pragma unroll
        for (int c4 = 0; c4 < 8; ++c4) {
            float4 av = *(const float4*)&s.A[cur][j][c4 * 4];        // broadcast x8
            float4 m0 = *(const float4*)&s.B[c4 * 4 + 0][kt];        // conflict-free
            float4 m1 = *(const float4*)&s.B[c4 * 4 + 1][kt];
            float4 m2 = *(const float4*)&s.B[c4 * 4 + 2][kt];
            float4 m3 = *(const float4*)&s.B[c4 * 4 + 3][kt];
            a0 += av.x * m0.x + av.y * m1.x + av.z * m2.x + av.w * m3.x;
            a1 += av.x * m0.y + av.y * m1.y + av.z * m2.y + av.w * m3.y;
            a2 += av.x * m0.z + av.y * m1.z + av.z * m2.z + av.w * m3.z;
            a3 += av.x * m0.w + av.y * m1.w + av.z * m2.w + av.w * m3.w;
        }
        *(float4*)&s.A[cur ^ 1][j][kt] = make_float4(a0, a1, a2, a3);
        cur ^= 1;
    }
    __syncthreads();
    *(float4*)(dst + tid * 4) = *(float4*)&s.A[cur][j][kt];
}

// Level 1: 128 blocks x product of 8 cores -> g_buf1
__global__ void __launch_bounds__(256) k_chain1(const float* __restrict__ cores) {
    chain_product_store<8>(cores, blockIdx.x * 8, g_buf1 + blockIdx.x * (BOND * BOND));
}

// Level 2: 16 blocks x product of 8 -> g_buf2
__global__ void __launch_bounds__(256) k_chain2() {
    chain_product_store<8>(g_buf1, blockIdx.x * 8, g_buf2 + blockIdx.x * (BOND * BOND));
}

// Level 3: warp 0 runs the 1x32 vector through the 16 remaining matrices via
// shuffle broadcast (no barriers, G double-buffered from L2); then the full
// block computes w = u @ projection.
__global__ void __launch_bounds__(256) k_finalize(const float* __restrict__ proj) {
    __shared__ float u_s[BOND];
    const int tid = threadIdx.x;

    if (tid < 32) {
        const int lane = tid;
        float v = 1.0f;                       // ones^T
        float g[BOND];                        // G_t[j][lane], j = 0..31
#pragma unroll
        for (int jj = 0; jj < BOND; ++jj)     // preload t = 0 (coalesced, L2-hot)
            g[jj] = g_buf2[jj * BOND + lane];

#pragma unroll
        for (int t = 0; t < 16; ++t) {
            float gn[BOND];
            if (t < 15) {                     // prefetch next matrix during FMA chain
#pragma unroll
                for (int jj = 0; jj < BOND; ++jj)
                    gn[jj] = g_buf2[(t + 1) * (BOND * BOND) + jj * BOND + lane];
            }
            float acc0 = 0.f, acc1 = 0.f;     // split chain: 2 accumulators
#pragma unroll
            for (int jj = 0; jj < BOND; jj += 2) {
                acc0 += __shfl_sync(0xffffffffu, v, jj)     * g[jj];
                acc1 += __shfl_sync(0xffffffffu, v, jj + 1) * g[jj + 1];
            }
            v = acc0 + acc1;
            if (t < 15) {
#pragma unroll
                for (int jj = 0; jj < BOND; ++jj) g[jj] = gn[jj];
            }
        }
        u_s[lane] = v;
    }
    __syncthreads();

    // w[o] = sum_k u[k] * proj[k][o]
    for (int o = tid; o < OUT_DIM; o += 256) {
        float acc = 0.f;
#pragma unroll
        for (int k = 0; k < BOND; ++k) acc += u_s[k] * proj[k * OUT_DIM + o];
        g_w[o] = acc;
    }
}

// Output: warp-per-row, no barriers. p[b] = prod(x[b,:]); out = p*w + bias.
__global__ void __launch_bounds__(256) k_output(const float* __restrict__ x,
                                                const float* __restrict__ bias,
                                                float* __restrict__ out) {
    const int warp = threadIdx.x >> 5;
    const int lane = threadIdx.x & 31;
    const long b   = (long)blockIdx.x * 8 + warp;

    const float* row = x + b * INPUT_DIM;
    float4 v[8];
#pragma unroll
    for (int i = 0; i < 8; ++i)               // 8 independent LDG.128, coalesced
        v[i] = *(const float4*)(row + (lane + 32 * i) * 4);

    float p = 1.f;
#pragma unroll
    for (int i = 0; i < 8; ++i)
        p *= (v[i].x * v[i].y) * (v[i].z * v[i].w);

#pragma unroll
    for (int off = 16; off; off >>= 1)        // warp product-reduce (all lanes get P)
        p *= __shfl_xor_sync(0xffffffffu, p, off);

    float* orow = out + b * OUT_DIM;
#pragma unroll
    for (int i = 0; i < 4; ++i) {             // 512 floats, coalesced float4 stores
        const int o4 = (lane + 32 * i) * 4;
        float4 wv = *(const float4*)(g_w + o4);
        float4 bv = *(const float4*)(bias + o4);
        float4 r;
        r.x = fmaf(p, wv.x, bv.x);
        r.y = fmaf(p, wv.y, bv.y);
        r.z = fmaf(p, wv.z, bv.z);
        r.w = fmaf(p, wv.w, bv.w);
        *(float4*)(orow + o4) = r;
    }
}

extern "C" void kernel_launch(void* const* d_in, const int* in_sizes, int n_in,
                              void* d_out, int out_size) {
    const float* inputs = (const float*)d_in[0];   // [4096, 1024]
    const float* cores  = (const float*)d_in[1];   // [1024, 32, 32]
    const float* proj   = (const float*)d_in[2];   // [32, 512]
    const float* bias   = (const float*)d_in[3];   // [512]
    float*       out    = (float*)d_out;           // [4096, 512]

    (void)in_sizes; (void)n_in; (void)out_size;

    k_chain1  <<<128, 256>>>(cores);
    k_chain2  <<<16,  256>>>();
    k_finalize<<<1,   256>>>(proj);
    k_output  <<<BATCH / 8, 256>>>(inputs, bias, out);
}